// round 14
// baseline (speedup 1.0000x reference)
#include <cuda_runtime.h>
#include <cuda_bf16.h>
#include <cstdint>

#define N_NODES 50000
#define MAX_EDGES 800000
#define F_IN 128
#define F_HID 256
#define F_OUT 64
#define K1 256   // GEMM K for both layers
#define N2 128   // GEMM2 N = [y | z]

typedef __nv_bfloat16 bf16;
typedef __nv_bfloat162 bf162;

// ---------------- scratch (device globals) ----------------
__device__ int   g_degi[N_NODES];     // zero at load; scan self-resets each call
__device__ int   g_cnt[N_NODES];      // fill cursors (scan seeds with row starts)
__device__ int   g_row[N_NODES + 1];
__device__ int   g_csr[MAX_EDGES];
__device__ bf16  g_a1hi[(size_t)N_NODES * K1];   // [agg1 | x] hi
__device__ bf16  g_a1lo[(size_t)N_NODES * K1];   // [agg1 | x] lo
__device__ bf16  g_hhi[(size_t)N_NODES * F_HID];
__device__ bf16  g_hlo[(size_t)N_NODES * F_HID];
__device__ float g_yz[(size_t)N_NODES * N2];     // [y(64) | z(64)]
// transposed weights: W^T[N][K]
__device__ bf16  g_w1thi[F_HID * K1];
__device__ bf16  g_w1tlo[F_HID * K1];
__device__ bf16  g_w2thi[N2 * F_HID];
__device__ bf16  g_w2tlo[N2 * F_HID];
__device__ float g_bias2[N2];

// ---------------- helpers ----------------
__device__ __forceinline__ void split_bf16(float v, bf16& hi, bf16& lo) {
    hi = __float2bfloat16_rn(v);
    lo = __float2bfloat16_rn(v - __bfloat162float(hi));
}

__device__ __forceinline__ void cp16(uint32_t dst, const void* src, int src_bytes) {
    asm volatile("cp.async.cg.shared.global [%0], [%1], 16, %2;"
                 :: "r"(dst), "l"(src), "r"(src_bytes) : "memory");
}

__device__ __forceinline__ void mma16816(float* d, const uint32_t* a, const uint32_t* b) {
    asm volatile(
        "mma.sync.aligned.m16n8k16.row.col.f32.bf16.bf16.f32 "
        "{%0,%1,%2,%3}, {%4,%5,%6,%7}, {%8,%9}, {%0,%1,%2,%3};"
        : "+f"(d[0]), "+f"(d[1]), "+f"(d[2]), "+f"(d[3])
        : "r"(a[0]), "r"(a[1]), "r"(a[2]), "r"(a[3]), "r"(b[0]), "r"(b[1]));
}

// ---------------- CSR build ----------------
__global__ void deg_kernel(const int* __restrict__ dst, int E) {
    int i = blockIdx.x * blockDim.x + threadIdx.x;
    if (i < E) atomicAdd(&g_degi[dst[i]], 1);
}

// single-block exclusive scan of g_degi -> g_row ; seeds g_cnt cursors ;
// self-resets g_degi to 0 for the next call (graph replay safe).
__global__ void scan_kernel(int E) {
    __shared__ int part[1024];
    const int T = 1024;
    const int chunk = (N_NODES + T - 1) / T;
    int t = threadIdx.x;
    int lo = t * chunk;
    int hi = min(lo + chunk, N_NODES);
    int s = 0;
    for (int i = lo; i < hi; i++) s += g_degi[i];
    part[t] = s;
    __syncthreads();
    for (int off = 1; off < T; off <<= 1) {
        int v = (t >= off) ? part[t - off] : 0;
        __syncthreads();
        part[t] += v;
        __syncthreads();
    }
    int running = (t == 0) ? 0 : part[t - 1];
    for (int i = lo; i < hi; i++) {
        int d = g_degi[i];
        g_row[i] = running;
        g_cnt[i] = running;   // cursor starts at row start
        g_degi[i] = 0;        // reset for next call
        running += d;
    }
    if (t == T - 1) g_row[N_NODES] = E;
}

__global__ void fill_csr_kernel(const int* __restrict__ src,
                                const int* __restrict__ dst, int E) {
    int i = blockIdx.x * blockDim.x + threadIdx.x;
    if (i >= E) return;
    int pos = atomicAdd(&g_cnt[dst[i]], 1);
    g_csr[pos] = src[i];
}

// ---------------- fused weight prep (transposed) + bias2 ----------------
__global__ void prep_w_kernel(const float* __restrict__ Wl1, const float* __restrict__ Wr1,
                              const float* __restrict__ Wl2, const float* __restrict__ Wr2,
                              const float* __restrict__ b2) {
    int i = blockIdx.x * blockDim.x + threadIdx.x;
    if (i < N2) g_bias2[i] = (i < F_OUT) ? 0.0f : b2[i - F_OUT];
    if (i < F_HID * K1) {
        int n = i / K1, k = i % K1;
        float v = (k < F_IN) ? Wl1[k * F_HID + n] : Wr1[(k - F_IN) * F_HID + n];
        bf16 h, l; split_bf16(v, h, l);
        g_w1thi[i] = h; g_w1tlo[i] = l;
    } else {
        int j = i - F_HID * K1;
        if (j < N2 * F_HID) {
            int n = j / F_HID, k = j % F_HID;
            float v = (n < F_OUT) ? Wl2[k * F_OUT + n] : Wr2[k * F_OUT + (n - F_OUT)];
            bf16 h, l; split_bf16(v, h, l);
            g_w2thi[j] = h; g_w2tlo[j] = l;
        }
    }
}

// ---------------- gather1 (+ fused x split): builds [agg1 | x] hi/lo ----------------
__global__ void gather1_kernel(const float* __restrict__ x) {
    int node = (blockIdx.x * blockDim.x + threadIdx.x) >> 5;
    if (node >= N_NODES) return;
    int lane = threadIdx.x & 31;
    int start = g_row[node], end = g_row[node + 1];

    float4 acc = make_float4(0.f, 0.f, 0.f, 0.f);
    int i = start;
    for (; i + 4 <= end; i += 4) {
        int s0 = __ldg(&g_csr[i]);
        int s1 = __ldg(&g_csr[i + 1]);
        int s2 = __ldg(&g_csr[i + 2]);
        int s3 = __ldg(&g_csr[i + 3]);
        float4 t0 = __ldg(&reinterpret_cast<const float4*>(x + (size_t)s0 * F_IN)[lane]);
        float4 t1 = __ldg(&reinterpret_cast<const float4*>(x + (size_t)s1 * F_IN)[lane]);
        float4 t2 = __ldg(&reinterpret_cast<const float4*>(x + (size_t)s2 * F_IN)[lane]);
        float4 t3 = __ldg(&reinterpret_cast<const float4*>(x + (size_t)s3 * F_IN)[lane]);
        acc.x += t0.x + t1.x + t2.x + t3.x;
        acc.y += t0.y + t1.y + t2.y + t3.y;
        acc.z += t0.z + t1.z + t2.z + t3.z;
        acc.w += t0.w + t1.w + t2.w + t3.w;
    }
    for (; i < end; i++) {
        int s = __ldg(&g_csr[i]);
        float4 t = __ldg(&reinterpret_cast<const float4*>(x + (size_t)s * F_IN)[lane]);
        acc.x += t.x; acc.y += t.y; acc.z += t.z; acc.w += t.w;
    }
    float inv = 1.0f / fmaxf((float)(end - start), 1.0f);
    acc.x *= inv; acc.y *= inv; acc.z *= inv; acc.w *= inv;

    bf16 h0, h1, h2, h3, l0, l1, l2, l3;
    split_bf16(acc.x, h0, l0); split_bf16(acc.y, h1, l1);
    split_bf16(acc.z, h2, l2); split_bf16(acc.w, h3, l3);
    size_t off = (size_t)node * K1 + lane * 4;
    *reinterpret_cast<bf162*>(&g_a1hi[off])     = bf162(h0, h1);
    *reinterpret_cast<bf162*>(&g_a1hi[off + 2]) = bf162(h2, h3);
    *reinterpret_cast<bf162*>(&g_a1lo[off])     = bf162(l0, l1);
    *reinterpret_cast<bf162*>(&g_a1lo[off + 2]) = bf162(l2, l3);

    // fused: split x[node] into cols 128..255
    float4 xv = __ldg(&reinterpret_cast<const float4*>(x + (size_t)node * F_IN)[lane]);
    split_bf16(xv.x, h0, l0); split_bf16(xv.y, h1, l1);
    split_bf16(xv.z, h2, l2); split_bf16(xv.w, h3, l3);
    off = (size_t)node * K1 + F_IN + lane * 4;
    *reinterpret_cast<bf162*>(&g_a1hi[off])     = bf162(h0, h1);
    *reinterpret_cast<bf162*>(&g_a1hi[off + 2]) = bf162(h2, h3);
    *reinterpret_cast<bf162*>(&g_a1lo[off])     = bf162(l0, l1);
    *reinterpret_cast<bf162*>(&g_a1lo[off + 2]) = bf162(l2, l3);
}

// ---------------- final: out = sigmoid(mean_agg(y) + z) ----------------
__global__ void final_kernel(float* __restrict__ out) {
    int node = (blockIdx.x * blockDim.x + threadIdx.x) >> 5;
    if (node >= N_NODES) return;
    int lane = threadIdx.x & 31;
    int start = g_row[node], end = g_row[node + 1];

    float2 acc = make_float2(0.f, 0.f);
    int i = start;
    for (; i + 4 <= end; i += 4) {
        int s0 = __ldg(&g_csr[i]);
        int s1 = __ldg(&g_csr[i + 1]);
        int s2 = __ldg(&g_csr[i + 2]);
        int s3 = __ldg(&g_csr[i + 3]);
        float2 t0 = __ldg(&reinterpret_cast<const float2*>(g_yz + (size_t)s0 * N2)[lane]);
        float2 t1 = __ldg(&reinterpret_cast<const float2*>(g_yz + (size_t)s1 * N2)[lane]);
        float2 t2 = __ldg(&reinterpret_cast<const float2*>(g_yz + (size_t)s2 * N2)[lane]);
        float2 t3 = __ldg(&reinterpret_cast<const float2*>(g_yz + (size_t)s3 * N2)[lane]);
        acc.x += t0.x + t1.x + t2.x + t3.x;
        acc.y += t0.y + t1.y + t2.y + t3.y;
    }
    for (; i < end; i++) {
        int s = __ldg(&g_csr[i]);
        float2 t = __ldg(&reinterpret_cast<const float2*>(g_yz + (size_t)s * N2)[lane]);
        acc.x += t.x; acc.y += t.y;
    }
    float inv = 1.0f / fmaxf((float)(end - start), 1.0f);
    float2 z = *reinterpret_cast<const float2*>(g_yz + (size_t)node * N2 + F_OUT + lane * 2);
    float v0 = acc.x * inv + z.x;
    float v1 = acc.y * inv + z.y;
    v0 = 1.0f / (1.0f + __expf(-v0));
    v1 = 1.0f / (1.0f + __expf(-v1));
    *reinterpret_cast<float2*>(out + (size_t)node * F_OUT + lane * 2) = make_float2(v0, v1);
}

// ---------------- pipelined split-bf16 tensor-core GEMM (R10 geometry) ----------------
// C = A @ Wt^T + bias.  A: hi/lo bf16 [M][KTOT] row-major.  Wt: hi/lo bf16 [N][KTOT].
// C ~= Ah*Wh + Ah*Wl + Al*Wh (f32 accumulate).  BM=BN=128, BK=32, 8 warps (2x4).
// OUTMODE 0: relu, split-store bf16 to (Chi,Clo) row stride c_stride.
// OUTMODE 2: linear, f32 store to Cf32 row stride N.
template <int BM, int BN, int KTOT, int OUTMODE>
__global__ __launch_bounds__(256)
void gemm_mma2_kernel(const bf16* __restrict__ Ahi, const bf16* __restrict__ Alo,
                      const bf16* __restrict__ Wthi, const bf16* __restrict__ Wtlo,
                      const float* __restrict__ bias,
                      float* __restrict__ Cf32, bf16* __restrict__ Chi,
                      bf16* __restrict__ Clo, int c_stride, int M, int N) {
    constexpr int BK = 32;
    constexpr int RS = 40;                      // smem row stride (bf16): 80B, conflict-free
    constexpr int NK = KTOT / BK;
    constexpr int A_ELEMS = 2 * 2 * BM * RS;    // stages x parts
    static_assert(BM == 128 && BN == 128, "tile");

    extern __shared__ char smraw[];
    const uint32_t smA = (uint32_t)__cvta_generic_to_shared(smraw);
    const uint32_t smW = smA + A_ELEMS * 2;     // bytes

    const int t = threadIdx.x;
    const int warp = t >> 5;
    const int lane = t & 31;
    const int wm = warp >> 2;                   // 0..1 (M dir)
    const int wn = warp & 3;                    // 0..3 (N dir)
    const int row0 = blockIdx.y * BM;
    const int col0 = blockIdx.x * BN;
    constexpr int WT_M = 64, WT_N = 32, MF = 4, NF = 4;

    float acc[MF][NF][4];
#pragma unroll
    for (int a = 0; a < MF; a++)
#pragma unroll
        for (int b = 0; b < NF; b++)
#pragma unroll
            for (int q = 0; q < 4; q++) acc[a][b][q] = 0.f;

    // ldmatrix lane-derived offsets
    const int aRow = lane & 15;
    const int aCol = (lane & 16) ? 8 : 0;
    const int bRow = lane & 7;
    const int bCol = (lane & 8) ? 8 : 0;

    auto loadStage = [&](int stage, int k0) {
#pragma unroll
        for (int j = 0; j < 4; j++) {           // A: 1024 16B chunks
            int cidx = t + 256 * j;
            int part = cidx >> 9;
            int rem = cidx & 511;
            int row = rem >> 2;
            int q = rem & 3;
            const bf16* srcb = part ? Alo : Ahi;
            int grow = row0 + row;
            uint32_t d = smA + (((stage * 2 + part) * BM + row) * RS + q * 8) * 2;
            const bf16* s = srcb + ((grow < M) ? ((size_t)grow * KTOT + k0 + q * 8) : 0);
            cp16(d, s, (grow < M) ? 16 : 0);
        }
#pragma unroll
        for (int j = 0; j < 4; j++) {           // W: 1024 16B chunks
            int cidx = t + 256 * j;
            int part = cidx >> 9;
            int rem = cidx & 511;
            int row = rem >> 2;                 // n index
            int q = rem & 3;
            const bf16* srcb = part ? Wtlo : Wthi;
            uint32_t d = smW + (((stage * 2 + part) * BN + row) * RS + q * 8) * 2;
            cp16(d, srcb + (size_t)(col0 + row) * KTOT + k0 + q * 8, 16);
        }
        asm volatile("cp.async.commit_group;" ::: "memory");
    };

    loadStage(0, 0);
    for (int ks = 0; ks < NK; ks++) {
        if (ks + 1 < NK) {
            loadStage((ks + 1) & 1, (ks + 1) * BK);
            asm volatile("cp.async.wait_group 1;" ::: "memory");
        } else {
            asm volatile("cp.async.wait_group 0;" ::: "memory");
        }
        __syncthreads();
        const int st = ks & 1;

#pragma unroll
        for (int kk = 0; kk < BK; kk += 16) {
            uint32_t ah[MF][4], al[MF][4];
#pragma unroll
            for (int mf = 0; mf < MF; mf++) {
                int r = wm * WT_M + mf * 16 + aRow;
                uint32_t ha = smA + (((st * 2 + 0) * BM + r) * RS + kk + aCol) * 2;
                uint32_t la = smA + (((st * 2 + 1) * BM + r) * RS + kk + aCol) * 2;
                asm volatile("ldmatrix.sync.aligned.m8n8.x4.shared.b16 {%0,%1,%2,%3}, [%4];"
                             : "=r"(ah[mf][0]), "=r"(ah[mf][1]), "=r"(ah[mf][2]), "=r"(ah[mf][3])
                             : "r"(ha));
                asm volatile("ldmatrix.sync.aligned.m8n8.x4.shared.b16 {%0,%1,%2,%3}, [%4];"
                             : "=r"(al[mf][0]), "=r"(al[mf][1]), "=r"(al[mf][2]), "=r"(al[mf][3])
                             : "r"(la));
            }
            uint32_t bh[NF][2], bl[NF][2];
#pragma unroll
            for (int nf = 0; nf < NF; nf++) {
                int n = wn * WT_N + nf * 8 + bRow;
                uint32_t hb = smW + (((st * 2 + 0) * BN + n) * RS + kk + bCol) * 2;
                uint32_t lb = smW + (((st * 2 + 1) * BN + n) * RS + kk + bCol) * 2;
                asm volatile("ldmatrix.sync.aligned.m8n8.x2.shared.b16 {%0,%1}, [%2];"
                             : "=r"(bh[nf][0]), "=r"(bh[nf][1]) : "r"(hb));
                asm volatile("ldmatrix.sync.aligned.m8n8.x2.shared.b16 {%0,%1}, [%2];"
                             : "=r"(bl[nf][0]), "=r"(bl[nf][1]) : "r"(lb));
            }
#pragma unroll
            for (int mf = 0; mf < MF; mf++)
#pragma unroll
                for (int nf = 0; nf < NF; nf++) {
                    mma16816(acc[mf][nf], ah[mf], bh[nf]);
                    mma16816(acc[mf][nf], ah[mf], bl[nf]);
                    mma16816(acc[mf][nf], al[mf], bh[nf]);
                }
        }
        __syncthreads();
    }

    // --- epilogue ---
    const int r = lane >> 2;
    const int c = (lane & 3) * 2;
#pragma unroll
    for (int mf = 0; mf < MF; mf++) {
#pragma unroll
        for (int nf = 0; nf < NF; nf++) {
#pragma unroll
            for (int p = 0; p < 2; p++) {
                int row = row0 + wm * WT_M + mf * 16 + r + p * 8;
                if (row >= M) continue;
                int colg = col0 + wn * WT_N + nf * 8 + c;
                float v0 = acc[mf][nf][2 * p]     + __ldg(&bias[colg]);
                float v1 = acc[mf][nf][2 * p + 1] + __ldg(&bias[colg + 1]);
                if (OUTMODE == 0) {
                    v0 = fmaxf(v0, 0.f);
                    v1 = fmaxf(v1, 0.f);
                    bf16 h0, h1, l0, l1;
                    split_bf16(v0, h0, l0);
                    split_bf16(v1, h1, l1);
                    size_t off = (size_t)row * c_stride + colg;
                    *reinterpret_cast<bf162*>(&Chi[off]) = bf162(h0, h1);
                    *reinterpret_cast<bf162*>(&Clo[off]) = bf162(l0, l1);
                } else {
                    size_t off = (size_t)row * N + colg;
                    Cf32[off]     = v0;
                    Cf32[off + 1] = v1;
                }
            }
        }
    }
}

// ---------------- launch ----------------
extern "C" void kernel_launch(void* const* d_in, const int* in_sizes, int n_in,
                              void* d_out, int out_size) {
    const float* x   = (const float*)d_in[0];
    const int*   ei  = (const int*)d_in[1];
    const float* Wl1 = (const float*)d_in[2];
    const float* Wr1 = (const float*)d_in[3];
    const float* b1  = (const float*)d_in[4];
    const float* Wl2 = (const float*)d_in[5];
    const float* Wr2 = (const float*)d_in[6];
    const float* b2  = (const float*)d_in[7];
    float* out = (float*)d_out;

    const int E = in_sizes[1] / 2;
    const int* src = ei;
    const int* dst = ei + E;

    bf16 *a1hi, *a1lo, *hhi, *hlo, *w1thi, *w1tlo, *w2thi, *w2tlo;
    float *yz, *bias2;
    cudaGetSymbolAddress((void**)&a1hi,  g_a1hi);
    cudaGetSymbolAddress((void**)&a1lo,  g_a1lo);
    cudaGetSymbolAddress((void**)&hhi,   g_hhi);
    cudaGetSymbolAddress((void**)&hlo,   g_hlo);
    cudaGetSymbolAddress((void**)&w1thi, g_w1thi);
    cudaGetSymbolAddress((void**)&w1tlo, g_w1tlo);
    cudaGetSymbolAddress((void**)&w2thi, g_w2thi);
    cudaGetSymbolAddress((void**)&w2tlo, g_w2tlo);
    cudaGetSymbolAddress((void**)&yz,    g_yz);
    cudaGetSymbolAddress((void**)&bias2, g_bias2);

    const int SMEM = 2 * (2 * 2 * 128 * 40 * 2);  // A + W regions = 81920 B
    cudaFuncSetAttribute(gemm_mma2_kernel<128, 128, K1, 0>,
                         cudaFuncAttributeMaxDynamicSharedMemorySize, SMEM);
    cudaFuncSetAttribute(gemm_mma2_kernel<128, 128, K1, 2>,
                         cudaFuncAttributeMaxDynamicSharedMemorySize, SMEM);

    // --- CSR build (scan self-resets g_degi; no zero kernel) ---
    deg_kernel<<<(E + 255) / 256, 256>>>(dst, E);
    scan_kernel<<<1, 1024>>>(E);
    fill_csr_kernel<<<(E + 255) / 256, 256>>>(src, dst, E);

    // --- weight prep (fused) ---
    prep_w_kernel<<<(F_HID * K1 + N2 * F_HID + 255) / 256, 256>>>(Wl1, Wr1, Wl2, Wr2, b2);

    const int gather_blocks = (N_NODES * 32 + 255) / 256;

    // --- layer 1: [agg1|x] then h = relu(A1 @ W1cat + b1) ---
    gather1_kernel<<<gather_blocks, 256>>>(x);
    {
        dim3 grid(F_HID / 128, (N_NODES + 127) / 128);
        gemm_mma2_kernel<128, 128, K1, 0><<<grid, 256, SMEM>>>(
            a1hi, a1lo, w1thi, w1tlo, b1,
            nullptr, hhi, hlo, F_HID, N_NODES, F_HID);
    }

    // --- layer 2 reordered: [y|z] = h @ [Wl2|Wr2] + [0|b2] ---
    {
        dim3 grid(N2 / 128, (N_NODES + 127) / 128);
        gemm_mma2_kernel<128, 128, K1, 2><<<grid, 256, SMEM>>>(
            hhi, hlo, w2thi, w2tlo, bias2,
            yz, nullptr, nullptr, 0, N_NODES, N2);
    }

    // --- final: out = sigmoid(mean_agg(y) + z) ---
    final_kernel<<<gather_blocks, 256>>>(out);
}

// round 15
// speedup vs baseline: 1.2028x; 1.2028x over previous
#include <cuda_runtime.h>
#include <cuda_bf16.h>
#include <cstdint>

#define N_NODES 50000
#define MAX_EDGES 800000
#define F_IN 128
#define F_HID 256
#define F_OUT 64
#define K1 256   // GEMM K for both layers
#define N2 128   // GEMM2 N = [y | z]

typedef __nv_bfloat16 bf16;
typedef __nv_bfloat162 bf162;

// ---------------- scratch (device globals) ----------------
__device__ int   g_degi[N_NODES];
__device__ int   g_cnt[N_NODES];
__device__ int   g_row[N_NODES + 1];
__device__ int   g_csr[MAX_EDGES];
__device__ bf16  g_a1hi[(size_t)N_NODES * K1];   // [agg1 | x] hi
__device__ bf16  g_a1lo[(size_t)N_NODES * K1];   // [agg1 | x] lo
__device__ bf16  g_hhi[(size_t)N_NODES * F_HID];
__device__ bf16  g_hlo[(size_t)N_NODES * F_HID];
__device__ float g_yz[(size_t)N_NODES * N2];     // [y(64) | z(64)]
// transposed weights: W^T[N][K]
__device__ bf16  g_w1thi[F_HID * K1];
__device__ bf16  g_w1tlo[F_HID * K1];
__device__ bf16  g_w2thi[N2 * F_HID];
__device__ bf16  g_w2tlo[N2 * F_HID];
__device__ float g_bias2[N2];

// ---------------- helpers ----------------
__device__ __forceinline__ void split_bf16(float v, bf16& hi, bf16& lo) {
    hi = __float2bfloat16_rn(v);
    lo = __float2bfloat16_rn(v - __bfloat162float(hi));
}

__device__ __forceinline__ void cp16(uint32_t dst, const void* src, int src_bytes) {
    asm volatile("cp.async.cg.shared.global [%0], [%1], 16, %2;"
                 :: "r"(dst), "l"(src), "r"(src_bytes) : "memory");
}

__device__ __forceinline__ void mma16816(float* d, const uint32_t* a, const uint32_t* b) {
    asm volatile(
        "mma.sync.aligned.m16n8k16.row.col.f32.bf16.bf16.f32 "
        "{%0,%1,%2,%3}, {%4,%5,%6,%7}, {%8,%9}, {%0,%1,%2,%3};"
        : "+f"(d[0]), "+f"(d[1]), "+f"(d[2]), "+f"(d[3])
        : "r"(a[0]), "r"(a[1]), "r"(a[2]), "r"(a[3]), "r"(b[0]), "r"(b[1]));
}

// ---------------- CSR build ----------------
__global__ void zero_counts_kernel() {
    int i = blockIdx.x * blockDim.x + threadIdx.x;
    if (i < N_NODES) { g_degi[i] = 0; g_cnt[i] = 0; }
}

__global__ void deg_kernel(const int* __restrict__ dst, int E) {
    int i = blockIdx.x * blockDim.x + threadIdx.x;
    if (i < E) atomicAdd(&g_degi[dst[i]], 1);
}

// single-block exclusive scan of g_degi -> g_row
__global__ void scan_kernel(int E) {
    __shared__ int part[1024];
    const int T = 1024;
    const int chunk = (N_NODES + T - 1) / T;
    int t = threadIdx.x;
    int lo = t * chunk;
    int hi = min(lo + chunk, N_NODES);
    int s = 0;
    for (int i = lo; i < hi; i++) s += g_degi[i];
    part[t] = s;
    __syncthreads();
    for (int off = 1; off < T; off <<= 1) {
        int v = (t >= off) ? part[t - off] : 0;
        __syncthreads();
        part[t] += v;
        __syncthreads();
    }
    int running = (t == 0) ? 0 : part[t - 1];
    for (int i = lo; i < hi; i++) {
        g_row[i] = running;
        running += g_degi[i];
    }
    if (t == T - 1) g_row[N_NODES] = E;
}

__global__ void fill_csr_kernel(const int* __restrict__ src,
                                const int* __restrict__ dst, int E) {
    int i = blockIdx.x * blockDim.x + threadIdx.x;
    if (i >= E) return;
    int d = dst[i];
    int pos = g_row[d] + atomicAdd(&g_cnt[d], 1);
    g_csr[pos] = src[i];
}

// ---------------- fused weight prep (transposed) + bias2 ----------------
__global__ void prep_w_kernel(const float* __restrict__ Wl1, const float* __restrict__ Wr1,
                              const float* __restrict__ Wl2, const float* __restrict__ Wr2,
                              const float* __restrict__ b2) {
    int i = blockIdx.x * blockDim.x + threadIdx.x;
    if (i < N2) g_bias2[i] = (i < F_OUT) ? 0.0f : b2[i - F_OUT];
    if (i < F_HID * K1) {
        int n = i / K1, k = i % K1;
        float v = (k < F_IN) ? Wl1[k * F_HID + n] : Wr1[(k - F_IN) * F_HID + n];
        bf16 h, l; split_bf16(v, h, l);
        g_w1thi[i] = h; g_w1tlo[i] = l;
    } else {
        int j = i - F_HID * K1;
        if (j < N2 * F_HID) {
            int n = j / F_HID, k = j % F_HID;
            float v = (n < F_OUT) ? Wl2[k * F_OUT + n] : Wr2[k * F_OUT + (n - F_OUT)];
            bf16 h, l; split_bf16(v, h, l);
            g_w2thi[j] = h; g_w2tlo[j] = l;
        }
    }
}

// ---------------- gather1 (+ fused x split): builds [agg1 | x] hi/lo ----------------
__global__ void gather1_kernel(const float* __restrict__ x) {
    int node = (blockIdx.x * blockDim.x + threadIdx.x) >> 5;
    if (node >= N_NODES) return;
    int lane = threadIdx.x & 31;
    int start = g_row[node], end = g_row[node + 1];

    float4 acc = make_float4(0.f, 0.f, 0.f, 0.f);
    int i = start;
    for (; i + 4 <= end; i += 4) {
        int s0 = __ldg(&g_csr[i]);
        int s1 = __ldg(&g_csr[i + 1]);
        int s2 = __ldg(&g_csr[i + 2]);
        int s3 = __ldg(&g_csr[i + 3]);
        float4 t0 = __ldg(&reinterpret_cast<const float4*>(x + (size_t)s0 * F_IN)[lane]);
        float4 t1 = __ldg(&reinterpret_cast<const float4*>(x + (size_t)s1 * F_IN)[lane]);
        float4 t2 = __ldg(&reinterpret_cast<const float4*>(x + (size_t)s2 * F_IN)[lane]);
        float4 t3 = __ldg(&reinterpret_cast<const float4*>(x + (size_t)s3 * F_IN)[lane]);
        acc.x += t0.x + t1.x + t2.x + t3.x;
        acc.y += t0.y + t1.y + t2.y + t3.y;
        acc.z += t0.z + t1.z + t2.z + t3.z;
        acc.w += t0.w + t1.w + t2.w + t3.w;
    }
    for (; i < end; i++) {
        int s = __ldg(&g_csr[i]);
        float4 t = __ldg(&reinterpret_cast<const float4*>(x + (size_t)s * F_IN)[lane]);
        acc.x += t.x; acc.y += t.y; acc.z += t.z; acc.w += t.w;
    }
    float inv = 1.0f / fmaxf((float)(end - start), 1.0f);
    acc.x *= inv; acc.y *= inv; acc.z *= inv; acc.w *= inv;

    bf16 h0, h1, h2, h3, l0, l1, l2, l3;
    split_bf16(acc.x, h0, l0); split_bf16(acc.y, h1, l1);
    split_bf16(acc.z, h2, l2); split_bf16(acc.w, h3, l3);
    size_t off = (size_t)node * K1 + lane * 4;
    *reinterpret_cast<bf162*>(&g_a1hi[off])     = bf162(h0, h1);
    *reinterpret_cast<bf162*>(&g_a1hi[off + 2]) = bf162(h2, h3);
    *reinterpret_cast<bf162*>(&g_a1lo[off])     = bf162(l0, l1);
    *reinterpret_cast<bf162*>(&g_a1lo[off + 2]) = bf162(l2, l3);

    // fused: split x[node] into cols 128..255
    float4 xv = __ldg(&reinterpret_cast<const float4*>(x + (size_t)node * F_IN)[lane]);
    split_bf16(xv.x, h0, l0); split_bf16(xv.y, h1, l1);
    split_bf16(xv.z, h2, l2); split_bf16(xv.w, h3, l3);
    off = (size_t)node * K1 + F_IN + lane * 4;
    *reinterpret_cast<bf162*>(&g_a1hi[off])     = bf162(h0, h1);
    *reinterpret_cast<bf162*>(&g_a1hi[off + 2]) = bf162(h2, h3);
    *reinterpret_cast<bf162*>(&g_a1lo[off])     = bf162(l0, l1);
    *reinterpret_cast<bf162*>(&g_a1lo[off + 2]) = bf162(l2, l3);
}

// ---------------- final: out = sigmoid(mean_agg(y) + z) ----------------
__global__ void final_kernel(float* __restrict__ out) {
    int node = (blockIdx.x * blockDim.x + threadIdx.x) >> 5;
    if (node >= N_NODES) return;
    int lane = threadIdx.x & 31;
    int start = g_row[node], end = g_row[node + 1];

    float2 acc = make_float2(0.f, 0.f);
    int i = start;
    for (; i + 4 <= end; i += 4) {
        int s0 = __ldg(&g_csr[i]);
        int s1 = __ldg(&g_csr[i + 1]);
        int s2 = __ldg(&g_csr[i + 2]);
        int s3 = __ldg(&g_csr[i + 3]);
        float2 t0 = __ldg(&reinterpret_cast<const float2*>(g_yz + (size_t)s0 * N2)[lane]);
        float2 t1 = __ldg(&reinterpret_cast<const float2*>(g_yz + (size_t)s1 * N2)[lane]);
        float2 t2 = __ldg(&reinterpret_cast<const float2*>(g_yz + (size_t)s2 * N2)[lane]);
        float2 t3 = __ldg(&reinterpret_cast<const float2*>(g_yz + (size_t)s3 * N2)[lane]);
        acc.x += t0.x + t1.x + t2.x + t3.x;
        acc.y += t0.y + t1.y + t2.y + t3.y;
    }
    for (; i < end; i++) {
        int s = __ldg(&g_csr[i]);
        float2 t = __ldg(&reinterpret_cast<const float2*>(g_yz + (size_t)s * N2)[lane]);
        acc.x += t.x; acc.y += t.y;
    }
    float inv = 1.0f / fmaxf((float)(end - start), 1.0f);
    float2 z = *reinterpret_cast<const float2*>(g_yz + (size_t)node * N2 + F_OUT + lane * 2);
    float v0 = acc.x * inv + z.x;
    float v1 = acc.y * inv + z.y;
    v0 = 1.0f / (1.0f + __expf(-v0));
    v1 = 1.0f / (1.0f + __expf(-v1));
    *reinterpret_cast<float2*>(out + (size_t)node * F_OUT + lane * 2) = make_float2(v0, v1);
}

// ---------------- pipelined split-bf16 tensor-core GEMM ----------------
// C = A @ Wt^T + bias.  A: hi/lo bf16 [M][KTOT] row-major.  Wt: hi/lo bf16 [N][KTOT].
// C ~= Ah*Wh + Ah*Wl + Al*Wh (f32 accumulate).  BM=BN=128, BK=32, 8 warps (2x4).
// OUTMODE 0: relu, split-store bf16 to (Chi,Clo) row stride c_stride.
// OUTMODE 2: linear, f32 store to Cf32 row stride N.
template <int BM, int BN, int KTOT, int OUTMODE>
__global__ __launch_bounds__(256)
void gemm_mma2_kernel(const bf16* __restrict__ Ahi, const bf16* __restrict__ Alo,
                      const bf16* __restrict__ Wthi, const bf16* __restrict__ Wtlo,
                      const float* __restrict__ bias,
                      float* __restrict__ Cf32, bf16* __restrict__ Chi,
                      bf16* __restrict__ Clo, int c_stride, int M, int N) {
    constexpr int BK = 32;
    constexpr int RS = 40;                      // smem row stride (bf16): 80B, conflict-free
    constexpr int NK = KTOT / BK;
    constexpr int A_ELEMS = 2 * 2 * BM * RS;    // stages x parts
    static_assert(BM == 128 && BN == 128, "tile");

    extern __shared__ char smraw[];
    const uint32_t smA = (uint32_t)__cvta_generic_to_shared(smraw);
    const uint32_t smW = smA + A_ELEMS * 2;     // bytes

    const int t = threadIdx.x;
    const int warp = t >> 5;
    const int lane = t & 31;
    const int wm = warp >> 2;                   // 0..1 (M dir)
    const int wn = warp & 3;                    // 0..3 (N dir)
    const int row0 = blockIdx.y * BM;
    const int col0 = blockIdx.x * BN;
    constexpr int WT_M = 64, WT_N = 32, MF = 4, NF = 4;

    float acc[MF][NF][4];
#pragma unroll
    for (int a = 0; a < MF; a++)
#pragma unroll
        for (int b = 0; b < NF; b++)
#pragma unroll
            for (int q = 0; q < 4; q++) acc[a][b][q] = 0.f;

    // ldmatrix lane-derived offsets
    const int aRow = lane & 15;
    const int aCol = (lane & 16) ? 8 : 0;
    const int bRow = lane & 7;
    const int bCol = (lane & 8) ? 8 : 0;

    auto loadStage = [&](int stage, int k0) {
#pragma unroll
        for (int j = 0; j < 4; j++) {           // A: 1024 16B chunks
            int cidx = t + 256 * j;
            int part = cidx >> 9;
            int rem = cidx & 511;
            int row = rem >> 2;
            int q = rem & 3;
            const bf16* srcb = part ? Alo : Ahi;
            int grow = row0 + row;
            uint32_t d = smA + (((stage * 2 + part) * BM + row) * RS + q * 8) * 2;
            const bf16* s = srcb + ((grow < M) ? ((size_t)grow * KTOT + k0 + q * 8) : 0);
            cp16(d, s, (grow < M) ? 16 : 0);
        }
#pragma unroll
        for (int j = 0; j < 4; j++) {           // W: 1024 16B chunks
            int cidx = t + 256 * j;
            int part = cidx >> 9;
            int rem = cidx & 511;
            int row = rem >> 2;                 // n index
            int q = rem & 3;
            const bf16* srcb = part ? Wtlo : Wthi;
            uint32_t d = smW + (((stage * 2 + part) * BN + row) * RS + q * 8) * 2;
            cp16(d, srcb + (size_t)(col0 + row) * KTOT + k0 + q * 8, 16);
        }
        asm volatile("cp.async.commit_group;" ::: "memory");
    };

    loadStage(0, 0);
    for (int ks = 0; ks < NK; ks++) {
        if (ks + 1 < NK) {
            loadStage((ks + 1) & 1, (ks + 1) * BK);
            asm volatile("cp.async.wait_group 1;" ::: "memory");
        } else {
            asm volatile("cp.async.wait_group 0;" ::: "memory");
        }
        __syncthreads();
        const int st = ks & 1;

#pragma unroll
        for (int kk = 0; kk < BK; kk += 16) {
            uint32_t ah[MF][4], al[MF][4];
#pragma unroll
            for (int mf = 0; mf < MF; mf++) {
                int r = wm * WT_M + mf * 16 + aRow;
                uint32_t ha = smA + (((st * 2 + 0) * BM + r) * RS + kk + aCol) * 2;
                uint32_t la = smA + (((st * 2 + 1) * BM + r) * RS + kk + aCol) * 2;
                asm volatile("ldmatrix.sync.aligned.m8n8.x4.shared.b16 {%0,%1,%2,%3}, [%4];"
                             : "=r"(ah[mf][0]), "=r"(ah[mf][1]), "=r"(ah[mf][2]), "=r"(ah[mf][3])
                             : "r"(ha));
                asm volatile("ldmatrix.sync.aligned.m8n8.x4.shared.b16 {%0,%1,%2,%3}, [%4];"
                             : "=r"(al[mf][0]), "=r"(al[mf][1]), "=r"(al[mf][2]), "=r"(al[mf][3])
                             : "r"(la));
            }
            uint32_t bh[NF][2], bl[NF][2];
#pragma unroll
            for (int nf = 0; nf < NF; nf++) {
                int n = wn * WT_N + nf * 8 + bRow;
                uint32_t hb = smW + (((st * 2 + 0) * BN + n) * RS + kk + bCol) * 2;
                uint32_t lb = smW + (((st * 2 + 1) * BN + n) * RS + kk + bCol) * 2;
                asm volatile("ldmatrix.sync.aligned.m8n8.x2.shared.b16 {%0,%1}, [%2];"
                             : "=r"(bh[nf][0]), "=r"(bh[nf][1]) : "r"(hb));
                asm volatile("ldmatrix.sync.aligned.m8n8.x2.shared.b16 {%0,%1}, [%2];"
                             : "=r"(bl[nf][0]), "=r"(bl[nf][1]) : "r"(lb));
            }
#pragma unroll
            for (int mf = 0; mf < MF; mf++)
#pragma unroll
                for (int nf = 0; nf < NF; nf++) {
                    mma16816(acc[mf][nf], ah[mf], bh[nf]);
                    mma16816(acc[mf][nf], ah[mf], bl[nf]);
                    mma16816(acc[mf][nf], al[mf], bh[nf]);
                }
        }
        __syncthreads();
    }

    // --- epilogue ---
    const int r = lane >> 2;
    const int c = (lane & 3) * 2;
#pragma unroll
    for (int mf = 0; mf < MF; mf++) {
#pragma unroll
        for (int nf = 0; nf < NF; nf++) {
#pragma unroll
            for (int p = 0; p < 2; p++) {
                int row = row0 + wm * WT_M + mf * 16 + r + p * 8;
                if (row >= M) continue;
                int colg = col0 + wn * WT_N + nf * 8 + c;
                float v0 = acc[mf][nf][2 * p]     + __ldg(&bias[colg]);
                float v1 = acc[mf][nf][2 * p + 1] + __ldg(&bias[colg + 1]);
                if (OUTMODE == 0) {
                    v0 = fmaxf(v0, 0.f);
                    v1 = fmaxf(v1, 0.f);
                    bf16 h0, h1, l0, l1;
                    split_bf16(v0, h0, l0);
                    split_bf16(v1, h1, l1);
                    size_t off = (size_t)row * c_stride + colg;
                    *reinterpret_cast<bf162*>(&Chi[off]) = bf162(h0, h1);
                    *reinterpret_cast<bf162*>(&Clo[off]) = bf162(l0, l1);
                } else {
                    size_t off = (size_t)row * N + colg;
                    Cf32[off]     = v0;
                    Cf32[off + 1] = v1;
                }
            }
        }
    }
}

// ---------------- launch ----------------
extern "C" void kernel_launch(void* const* d_in, const int* in_sizes, int n_in,
                              void* d_out, int out_size) {
    const float* x   = (const float*)d_in[0];
    const int*   ei  = (const int*)d_in[1];
    const float* Wl1 = (const float*)d_in[2];
    const float* Wr1 = (const float*)d_in[3];
    const float* b1  = (const float*)d_in[4];
    const float* Wl2 = (const float*)d_in[5];
    const float* Wr2 = (const float*)d_in[6];
    const float* b2  = (const float*)d_in[7];
    float* out = (float*)d_out;

    const int E = in_sizes[1] / 2;
    const int* src = ei;
    const int* dst = ei + E;

    bf16 *a1hi, *a1lo, *hhi, *hlo, *w1thi, *w1tlo, *w2thi, *w2tlo;
    float *yz, *bias2;
    cudaGetSymbolAddress((void**)&a1hi,  g_a1hi);
    cudaGetSymbolAddress((void**)&a1lo,  g_a1lo);
    cudaGetSymbolAddress((void**)&hhi,   g_hhi);
    cudaGetSymbolAddress((void**)&hlo,   g_hlo);
    cudaGetSymbolAddress((void**)&w1thi, g_w1thi);
    cudaGetSymbolAddress((void**)&w1tlo, g_w1tlo);
    cudaGetSymbolAddress((void**)&w2thi, g_w2thi);
    cudaGetSymbolAddress((void**)&w2tlo, g_w2tlo);
    cudaGetSymbolAddress((void**)&yz,    g_yz);
    cudaGetSymbolAddress((void**)&bias2, g_bias2);

    const int SMEM = 2 * (2 * 2 * 128 * 40 * 2);  // A + W regions = 81920 B
    cudaFuncSetAttribute(gemm_mma2_kernel<128, 128, K1, 0>,
                         cudaFuncAttributeMaxDynamicSharedMemorySize, SMEM);
    cudaFuncSetAttribute(gemm_mma2_kernel<128, 128, K1, 2>,
                         cudaFuncAttributeMaxDynamicSharedMemorySize, SMEM);

    // --- weight prep first (off the CSR critical path) ---
    prep_w_kernel<<<(F_HID * K1 + N2 * F_HID + 255) / 256, 256>>>(Wl1, Wr1, Wl2, Wr2, b2);

    // --- CSR build ---
    zero_counts_kernel<<<(N_NODES + 255) / 256, 256>>>();
    deg_kernel<<<(E + 255) / 256, 256>>>(dst, E);
    scan_kernel<<<1, 1024>>>(E);
    fill_csr_kernel<<<(E + 255) / 256, 256>>>(src, dst, E);

    const int gather_blocks = (N_NODES * 32 + 255) / 256;

    // --- layer 1: [agg1|x] then h = relu(A1 @ W1cat + b1) ---
    gather1_kernel<<<gather_blocks, 256>>>(x);
    {
        dim3 grid(F_HID / 128, (N_NODES + 127) / 128);
        gemm_mma2_kernel<128, 128, K1, 0><<<grid, 256, SMEM>>>(
            a1hi, a1lo, w1thi, w1tlo, b1,
            nullptr, hhi, hlo, F_HID, N_NODES, F_HID);
    }

    // --- layer 2 reordered: [y|z] = h @ [Wl2|Wr2] + [0|b2] ---
    {
        dim3 grid(N2 / 128, (N_NODES + 127) / 128);
        gemm_mma2_kernel<128, 128, K1, 2><<<grid, 256, SMEM>>>(
            hhi, hlo, w2thi, w2tlo, bias2,
            yz, nullptr, nullptr, 0, N_NODES, N2);
    }

    // --- final: out = sigmoid(mean_agg(y) + z) ---
    final_kernel<<<gather_blocks, 256>>>(out);
}

// round 16
// speedup vs baseline: 1.4246x; 1.1843x over previous
#include <cuda_runtime.h>
#include <cuda_bf16.h>
#include <cstdint>

#define N_NODES 50000
#define MAX_EDGES 800000
#define F_IN 128
#define F_HID 256
#define F_OUT 64
#define K1 256   // GEMM K for both layers
#define N2 128   // GEMM2 N = [y | z]

#define SCAN_B 512
#define SCAN_NB ((N_NODES + SCAN_B - 1) / SCAN_B)   // 98

typedef __nv_bfloat16 bf16;
typedef __nv_bfloat162 bf162;

// ---------------- scratch (device globals) ----------------
__device__ int   g_degi[N_NODES];
__device__ int   g_cnt[N_NODES];
__device__ int   g_row[N_NODES + 1];
__device__ int   g_bsum[128];
__device__ int   g_boff[128];
__device__ int   g_csr[MAX_EDGES];
__device__ bf16  g_a1hi[(size_t)N_NODES * K1];   // [agg1 | x] hi
__device__ bf16  g_a1lo[(size_t)N_NODES * K1];   // [agg1 | x] lo
__device__ bf16  g_hhi[(size_t)N_NODES * F_HID];
__device__ bf16  g_hlo[(size_t)N_NODES * F_HID];
__device__ float g_yz[(size_t)N_NODES * N2];     // [y(64) | z(64)]
// transposed weights: W^T[N][K]
__device__ bf16  g_w1thi[F_HID * K1];
__device__ bf16  g_w1tlo[F_HID * K1];
__device__ bf16  g_w2thi[N2 * F_HID];
__device__ bf16  g_w2tlo[N2 * F_HID];
__device__ float g_bias2[N2];

// ---------------- helpers ----------------
__device__ __forceinline__ void split_bf16(float v, bf16& hi, bf16& lo) {
    hi = __float2bfloat16_rn(v);
    lo = __float2bfloat16_rn(v - __bfloat162float(hi));
}

__device__ __forceinline__ void cp16(uint32_t dst, const void* src, int src_bytes) {
    asm volatile("cp.async.cg.shared.global [%0], [%1], 16, %2;"
                 :: "r"(dst), "l"(src), "r"(src_bytes) : "memory");
}

__device__ __forceinline__ void mma16816(float* d, const uint32_t* a, const uint32_t* b) {
    asm volatile(
        "mma.sync.aligned.m16n8k16.row.col.f32.bf16.bf16.f32 "
        "{%0,%1,%2,%3}, {%4,%5,%6,%7}, {%8,%9}, {%0,%1,%2,%3};"
        : "+f"(d[0]), "+f"(d[1]), "+f"(d[2]), "+f"(d[3])
        : "r"(a[0]), "r"(a[1]), "r"(a[2]), "r"(a[3]), "r"(b[0]), "r"(b[1]));
}

// ---------------- CSR build ----------------
__global__ void zero_counts_kernel() {
    int i = blockIdx.x * blockDim.x + threadIdx.x;
    if (i < N_NODES) { g_degi[i] = 0; g_cnt[i] = 0; }
}

__global__ void deg_kernel(const int* __restrict__ dst, int E) {
    int i = blockIdx.x * blockDim.x + threadIdx.x;
    if (i < E) atomicAdd(&g_degi[dst[i]], 1);
}

// ---- two-level scan: stage 1 — per-block sums (full-chip parallel) ----
__global__ void scan1_kernel() {
    __shared__ int s[SCAN_B];
    int i = blockIdx.x * SCAN_B + threadIdx.x;
    s[threadIdx.x] = (i < N_NODES) ? g_degi[i] : 0;
    __syncthreads();
#pragma unroll
    for (int off = SCAN_B / 2; off > 0; off >>= 1) {
        if (threadIdx.x < off) s[threadIdx.x] += s[threadIdx.x + off];
        __syncthreads();
    }
    if (threadIdx.x == 0) g_bsum[blockIdx.x] = s[0];
}

// ---- stage 2 — exclusive scan of 98 block sums (tiny single block) ----
__global__ void scan2_kernel(int E) {
    __shared__ int s[128];
    int t = threadIdx.x;
    s[t] = (t < SCAN_NB) ? g_bsum[t] : 0;
    __syncthreads();
    for (int off = 1; off < 128; off <<= 1) {
        int u = (t >= off) ? s[t - off] : 0;
        __syncthreads();
        s[t] += u;
        __syncthreads();
    }
    if (t < SCAN_NB) g_boff[t] = (t == 0) ? 0 : s[t - 1];
    if (t == 0) g_row[N_NODES] = E;
}

// ---- stage 3 — intra-block exclusive scan + block offset -> g_row ----
__global__ void scan3_kernel() {
    __shared__ int s[SCAN_B];
    int b = blockIdx.x;
    int i = b * SCAN_B + threadIdx.x;
    int v = (i < N_NODES) ? g_degi[i] : 0;
    s[threadIdx.x] = v;
    __syncthreads();
    for (int off = 1; off < SCAN_B; off <<= 1) {
        int u = (threadIdx.x >= off) ? s[threadIdx.x - off] : 0;
        __syncthreads();
        s[threadIdx.x] += u;
        __syncthreads();
    }
    if (i < N_NODES) g_row[i] = g_boff[b] + s[threadIdx.x] - v;  // exclusive
}

__global__ void fill_csr_kernel(const int* __restrict__ src,
                                const int* __restrict__ dst, int E) {
    int i = blockIdx.x * blockDim.x + threadIdx.x;
    if (i >= E) return;
    int d = dst[i];
    int pos = g_row[d] + atomicAdd(&g_cnt[d], 1);
    g_csr[pos] = src[i];
}

// ---------------- fused weight prep (transposed) + bias2 ----------------
__global__ void prep_w_kernel(const float* __restrict__ Wl1, const float* __restrict__ Wr1,
                              const float* __restrict__ Wl2, const float* __restrict__ Wr2,
                              const float* __restrict__ b2) {
    int i = blockIdx.x * blockDim.x + threadIdx.x;
    if (i < N2) g_bias2[i] = (i < F_OUT) ? 0.0f : b2[i - F_OUT];
    if (i < F_HID * K1) {
        int n = i / K1, k = i % K1;
        float v = (k < F_IN) ? Wl1[k * F_HID + n] : Wr1[(k - F_IN) * F_HID + n];
        bf16 h, l; split_bf16(v, h, l);
        g_w1thi[i] = h; g_w1tlo[i] = l;
    } else {
        int j = i - F_HID * K1;
        if (j < N2 * F_HID) {
            int n = j / F_HID, k = j % F_HID;
            float v = (n < F_OUT) ? Wl2[k * F_OUT + n] : Wr2[k * F_OUT + (n - F_OUT)];
            bf16 h, l; split_bf16(v, h, l);
            g_w2thi[j] = h; g_w2tlo[j] = l;
        }
    }
}

// ---------------- gather1 (+ fused x split): builds [agg1 | x] hi/lo ----------------
__global__ void gather1_kernel(const float* __restrict__ x) {
    int node = (blockIdx.x * blockDim.x + threadIdx.x) >> 5;
    if (node >= N_NODES) return;
    int lane = threadIdx.x & 31;
    int start = g_row[node], end = g_row[node + 1];

    float4 acc = make_float4(0.f, 0.f, 0.f, 0.f);
    int i = start;
    for (; i + 4 <= end; i += 4) {
        int s0 = __ldg(&g_csr[i]);
        int s1 = __ldg(&g_csr[i + 1]);
        int s2 = __ldg(&g_csr[i + 2]);
        int s3 = __ldg(&g_csr[i + 3]);
        float4 t0 = __ldg(&reinterpret_cast<const float4*>(x + (size_t)s0 * F_IN)[lane]);
        float4 t1 = __ldg(&reinterpret_cast<const float4*>(x + (size_t)s1 * F_IN)[lane]);
        float4 t2 = __ldg(&reinterpret_cast<const float4*>(x + (size_t)s2 * F_IN)[lane]);
        float4 t3 = __ldg(&reinterpret_cast<const float4*>(x + (size_t)s3 * F_IN)[lane]);
        acc.x += t0.x + t1.x + t2.x + t3.x;
        acc.y += t0.y + t1.y + t2.y + t3.y;
        acc.z += t0.z + t1.z + t2.z + t3.z;
        acc.w += t0.w + t1.w + t2.w + t3.w;
    }
    for (; i < end; i++) {
        int s = __ldg(&g_csr[i]);
        float4 t = __ldg(&reinterpret_cast<const float4*>(x + (size_t)s * F_IN)[lane]);
        acc.x += t.x; acc.y += t.y; acc.z += t.z; acc.w += t.w;
    }
    float inv = 1.0f / fmaxf((float)(end - start), 1.0f);
    acc.x *= inv; acc.y *= inv; acc.z *= inv; acc.w *= inv;

    bf16 h0, h1, h2, h3, l0, l1, l2, l3;
    split_bf16(acc.x, h0, l0); split_bf16(acc.y, h1, l1);
    split_bf16(acc.z, h2, l2); split_bf16(acc.w, h3, l3);
    size_t off = (size_t)node * K1 + lane * 4;
    *reinterpret_cast<bf162*>(&g_a1hi[off])     = bf162(h0, h1);
    *reinterpret_cast<bf162*>(&g_a1hi[off + 2]) = bf162(h2, h3);
    *reinterpret_cast<bf162*>(&g_a1lo[off])     = bf162(l0, l1);
    *reinterpret_cast<bf162*>(&g_a1lo[off + 2]) = bf162(l2, l3);

    // fused: split x[node] into cols 128..255
    float4 xv = __ldg(&reinterpret_cast<const float4*>(x + (size_t)node * F_IN)[lane]);
    split_bf16(xv.x, h0, l0); split_bf16(xv.y, h1, l1);
    split_bf16(xv.z, h2, l2); split_bf16(xv.w, h3, l3);
    off = (size_t)node * K1 + F_IN + lane * 4;
    *reinterpret_cast<bf162*>(&g_a1hi[off])     = bf162(h0, h1);
    *reinterpret_cast<bf162*>(&g_a1hi[off + 2]) = bf162(h2, h3);
    *reinterpret_cast<bf162*>(&g_a1lo[off])     = bf162(l0, l1);
    *reinterpret_cast<bf162*>(&g_a1lo[off + 2]) = bf162(l2, l3);
}

// ---------------- final: out = sigmoid(mean_agg(y) + z) ----------------
__global__ void final_kernel(float* __restrict__ out) {
    int node = (blockIdx.x * blockDim.x + threadIdx.x) >> 5;
    if (node >= N_NODES) return;
    int lane = threadIdx.x & 31;
    int start = g_row[node], end = g_row[node + 1];

    float2 acc = make_float2(0.f, 0.f);
    int i = start;
    for (; i + 4 <= end; i += 4) {
        int s0 = __ldg(&g_csr[i]);
        int s1 = __ldg(&g_csr[i + 1]);
        int s2 = __ldg(&g_csr[i + 2]);
        int s3 = __ldg(&g_csr[i + 3]);
        float2 t0 = __ldg(&reinterpret_cast<const float2*>(g_yz + (size_t)s0 * N2)[lane]);
        float2 t1 = __ldg(&reinterpret_cast<const float2*>(g_yz + (size_t)s1 * N2)[lane]);
        float2 t2 = __ldg(&reinterpret_cast<const float2*>(g_yz + (size_t)s2 * N2)[lane]);
        float2 t3 = __ldg(&reinterpret_cast<const float2*>(g_yz + (size_t)s3 * N2)[lane]);
        acc.x += t0.x + t1.x + t2.x + t3.x;
        acc.y += t0.y + t1.y + t2.y + t3.y;
    }
    for (; i < end; i++) {
        int s = __ldg(&g_csr[i]);
        float2 t = __ldg(&reinterpret_cast<const float2*>(g_yz + (size_t)s * N2)[lane]);
        acc.x += t.x; acc.y += t.y;
    }
    float inv = 1.0f / fmaxf((float)(end - start), 1.0f);
    float2 z = *reinterpret_cast<const float2*>(g_yz + (size_t)node * N2 + F_OUT + lane * 2);
    float v0 = acc.x * inv + z.x;
    float v1 = acc.y * inv + z.y;
    v0 = 1.0f / (1.0f + __expf(-v0));
    v1 = 1.0f / (1.0f + __expf(-v1));
    *reinterpret_cast<float2*>(out + (size_t)node * F_OUT + lane * 2) = make_float2(v0, v1);
}

// ---------------- pipelined split-bf16 tensor-core GEMM ----------------
// C = A @ Wt^T + bias.  A: hi/lo bf16 [M][KTOT] row-major.  Wt: hi/lo bf16 [N][KTOT].
// C ~= Ah*Wh + Ah*Wl + Al*Wh (f32 accumulate).  BM=BN=128, BK=32, 8 warps (2x4).
// OUTMODE 0: relu, split-store bf16 to (Chi,Clo) row stride c_stride.
// OUTMODE 2: linear, f32 store to Cf32 row stride N.
template <int BM, int BN, int KTOT, int OUTMODE>
__global__ __launch_bounds__(256)
void gemm_mma2_kernel(const bf16* __restrict__ Ahi, const bf16* __restrict__ Alo,
                      const bf16* __restrict__ Wthi, const bf16* __restrict__ Wtlo,
                      const float* __restrict__ bias,
                      float* __restrict__ Cf32, bf16* __restrict__ Chi,
                      bf16* __restrict__ Clo, int c_stride, int M, int N) {
    constexpr int BK = 32;
    constexpr int RS = 40;                      // smem row stride (bf16): 80B, conflict-free
    constexpr int NK = KTOT / BK;
    constexpr int A_ELEMS = 2 * 2 * BM * RS;    // stages x parts
    static_assert(BM == 128 && BN == 128, "tile");

    extern __shared__ char smraw[];
    const uint32_t smA = (uint32_t)__cvta_generic_to_shared(smraw);
    const uint32_t smW = smA + A_ELEMS * 2;     // bytes

    const int t = threadIdx.x;
    const int warp = t >> 5;
    const int lane = t & 31;
    const int wm = warp >> 2;                   // 0..1 (M dir)
    const int wn = warp & 3;                    // 0..3 (N dir)
    const int row0 = blockIdx.y * BM;
    const int col0 = blockIdx.x * BN;
    constexpr int WT_M = 64, WT_N = 32, MF = 4, NF = 4;

    float acc[MF][NF][4];
#pragma unroll
    for (int a = 0; a < MF; a++)
#pragma unroll
        for (int b = 0; b < NF; b++)
#pragma unroll
            for (int q = 0; q < 4; q++) acc[a][b][q] = 0.f;

    // ldmatrix lane-derived offsets
    const int aRow = lane & 15;
    const int aCol = (lane & 16) ? 8 : 0;
    const int bRow = lane & 7;
    const int bCol = (lane & 8) ? 8 : 0;

    auto loadStage = [&](int stage, int k0) {
#pragma unroll
        for (int j = 0; j < 4; j++) {           // A: 1024 16B chunks
            int cidx = t + 256 * j;
            int part = cidx >> 9;
            int rem = cidx & 511;
            int row = rem >> 2;
            int q = rem & 3;
            const bf16* srcb = part ? Alo : Ahi;
            int grow = row0 + row;
            uint32_t d = smA + (((stage * 2 + part) * BM + row) * RS + q * 8) * 2;
            const bf16* s = srcb + ((grow < M) ? ((size_t)grow * KTOT + k0 + q * 8) : 0);
            cp16(d, s, (grow < M) ? 16 : 0);
        }
#pragma unroll
        for (int j = 0; j < 4; j++) {           // W: 1024 16B chunks
            int cidx = t + 256 * j;
            int part = cidx >> 9;
            int rem = cidx & 511;
            int row = rem >> 2;                 // n index
            int q = rem & 3;
            const bf16* srcb = part ? Wtlo : Wthi;
            uint32_t d = smW + (((stage * 2 + part) * BN + row) * RS + q * 8) * 2;
            cp16(d, srcb + (size_t)(col0 + row) * KTOT + k0 + q * 8, 16);
        }
        asm volatile("cp.async.commit_group;" ::: "memory");
    };

    loadStage(0, 0);
    for (int ks = 0; ks < NK; ks++) {
        if (ks + 1 < NK) {
            loadStage((ks + 1) & 1, (ks + 1) * BK);
            asm volatile("cp.async.wait_group 1;" ::: "memory");
        } else {
            asm volatile("cp.async.wait_group 0;" ::: "memory");
        }
        __syncthreads();
        const int st = ks & 1;

#pragma unroll
        for (int kk = 0; kk < BK; kk += 16) {
            uint32_t ah[MF][4], al[MF][4];
#pragma unroll
            for (int mf = 0; mf < MF; mf++) {
                int r = wm * WT_M + mf * 16 + aRow;
                uint32_t ha = smA + (((st * 2 + 0) * BM + r) * RS + kk + aCol) * 2;
                uint32_t la = smA + (((st * 2 + 1) * BM + r) * RS + kk + aCol) * 2;
                asm volatile("ldmatrix.sync.aligned.m8n8.x4.shared.b16 {%0,%1,%2,%3}, [%4];"
                             : "=r"(ah[mf][0]), "=r"(ah[mf][1]), "=r"(ah[mf][2]), "=r"(ah[mf][3])
                             : "r"(ha));
                asm volatile("ldmatrix.sync.aligned.m8n8.x4.shared.b16 {%0,%1,%2,%3}, [%4];"
                             : "=r"(al[mf][0]), "=r"(al[mf][1]), "=r"(al[mf][2]), "=r"(al[mf][3])
                             : "r"(la));
            }
            uint32_t bh[NF][2], bl[NF][2];
#pragma unroll
            for (int nf = 0; nf < NF; nf++) {
                int n = wn * WT_N + nf * 8 + bRow;
                uint32_t hb = smW + (((st * 2 + 0) * BN + n) * RS + kk + bCol) * 2;
                uint32_t lb = smW + (((st * 2 + 1) * BN + n) * RS + kk + bCol) * 2;
                asm volatile("ldmatrix.sync.aligned.m8n8.x2.shared.b16 {%0,%1}, [%2];"
                             : "=r"(bh[nf][0]), "=r"(bh[nf][1]) : "r"(hb));
                asm volatile("ldmatrix.sync.aligned.m8n8.x2.shared.b16 {%0,%1}, [%2];"
                             : "=r"(bl[nf][0]), "=r"(bl[nf][1]) : "r"(lb));
            }
#pragma unroll
            for (int mf = 0; mf < MF; mf++)
#pragma unroll
                for (int nf = 0; nf < NF; nf++) {
                    mma16816(acc[mf][nf], ah[mf], bh[nf]);
                    mma16816(acc[mf][nf], ah[mf], bl[nf]);
                    mma16816(acc[mf][nf], al[mf], bh[nf]);
                }
        }
        __syncthreads();
    }

    // --- epilogue ---
    const int r = lane >> 2;
    const int c = (lane & 3) * 2;
#pragma unroll
    for (int mf = 0; mf < MF; mf++) {
#pragma unroll
        for (int nf = 0; nf < NF; nf++) {
#pragma unroll
            for (int p = 0; p < 2; p++) {
                int row = row0 + wm * WT_M + mf * 16 + r + p * 8;
                if (row >= M) continue;
                int colg = col0 + wn * WT_N + nf * 8 + c;
                float v0 = acc[mf][nf][2 * p]     + __ldg(&bias[colg]);
                float v1 = acc[mf][nf][2 * p + 1] + __ldg(&bias[colg + 1]);
                if (OUTMODE == 0) {
                    v0 = fmaxf(v0, 0.f);
                    v1 = fmaxf(v1, 0.f);
                    bf16 h0, h1, l0, l1;
                    split_bf16(v0, h0, l0);
                    split_bf16(v1, h1, l1);
                    size_t off = (size_t)row * c_stride + colg;
                    *reinterpret_cast<bf162*>(&Chi[off]) = bf162(h0, h1);
                    *reinterpret_cast<bf162*>(&Clo[off]) = bf162(l0, l1);
                } else {
                    size_t off = (size_t)row * N + colg;
                    Cf32[off]     = v0;
                    Cf32[off + 1] = v1;
                }
            }
        }
    }
}

// ---------------- launch ----------------
extern "C" void kernel_launch(void* const* d_in, const int* in_sizes, int n_in,
                              void* d_out, int out_size) {
    const float* x   = (const float*)d_in[0];
    const int*   ei  = (const int*)d_in[1];
    const float* Wl1 = (const float*)d_in[2];
    const float* Wr1 = (const float*)d_in[3];
    const float* b1  = (const float*)d_in[4];
    const float* Wl2 = (const float*)d_in[5];
    const float* Wr2 = (const float*)d_in[6];
    const float* b2  = (const float*)d_in[7];
    float* out = (float*)d_out;

    const int E = in_sizes[1] / 2;
    const int* src = ei;
    const int* dst = ei + E;

    bf16 *a1hi, *a1lo, *hhi, *hlo, *w1thi, *w1tlo, *w2thi, *w2tlo;
    float *yz, *bias2;
    cudaGetSymbolAddress((void**)&a1hi,  g_a1hi);
    cudaGetSymbolAddress((void**)&a1lo,  g_a1lo);
    cudaGetSymbolAddress((void**)&hhi,   g_hhi);
    cudaGetSymbolAddress((void**)&hlo,   g_hlo);
    cudaGetSymbolAddress((void**)&w1thi, g_w1thi);
    cudaGetSymbolAddress((void**)&w1tlo, g_w1tlo);
    cudaGetSymbolAddress((void**)&w2thi, g_w2thi);
    cudaGetSymbolAddress((void**)&w2tlo, g_w2tlo);
    cudaGetSymbolAddress((void**)&yz,    g_yz);
    cudaGetSymbolAddress((void**)&bias2, g_bias2);

    const int SMEM = 2 * (2 * 2 * 128 * 40 * 2);  // A + W regions = 81920 B
    cudaFuncSetAttribute(gemm_mma2_kernel<128, 128, K1, 0>,
                         cudaFuncAttributeMaxDynamicSharedMemorySize, SMEM);
    cudaFuncSetAttribute(gemm_mma2_kernel<128, 128, K1, 2>,
                         cudaFuncAttributeMaxDynamicSharedMemorySize, SMEM);

    // --- weight prep first (off the CSR critical path) ---
    prep_w_kernel<<<(F_HID * K1 + N2 * F_HID + 255) / 256, 256>>>(Wl1, Wr1, Wl2, Wr2, b2);

    // --- CSR build (two-level parallel scan) ---
    zero_counts_kernel<<<(N_NODES + 255) / 256, 256>>>();
    deg_kernel<<<(E + 255) / 256, 256>>>(dst, E);
    scan1_kernel<<<SCAN_NB, SCAN_B>>>();
    scan2_kernel<<<1, 128>>>(E);
    scan3_kernel<<<SCAN_NB, SCAN_B>>>();
    fill_csr_kernel<<<(E + 255) / 256, 256>>>(src, dst, E);

    const int gather_blocks = (N_NODES * 32 + 255) / 256;

    // --- layer 1: [agg1|x] then h = relu(A1 @ W1cat + b1) ---
    gather1_kernel<<<gather_blocks, 256>>>(x);
    {
        dim3 grid(F_HID / 128, (N_NODES + 127) / 128);
        gemm_mma2_kernel<128, 128, K1, 0><<<grid, 256, SMEM>>>(
            a1hi, a1lo, w1thi, w1tlo, b1,
            nullptr, hhi, hlo, F_HID, N_NODES, F_HID);
    }

    // --- layer 2 reordered: [y|z] = h @ [Wl2|Wr2] + [0|b2] ---
    {
        dim3 grid(N2 / 128, (N_NODES + 127) / 128);
        gemm_mma2_kernel<128, 128, K1, 2><<<grid, 256, SMEM>>>(
            hhi, hlo, w2thi, w2tlo, bias2,
            yz, nullptr, nullptr, 0, N_NODES, N2);
    }

    // --- final: out = sigmoid(mean_agg(y) + z) ---
    final_kernel<<<gather_blocks, 256>>>(out);
}